// round 1
// baseline (speedup 1.0000x reference)
#include <cuda_runtime.h>
#include <cuda_bf16.h>
#include <cstdint>

#define N_POINTS 131072
#define N_NODES  2048
#define K_SEL    32
#define CAP      256   // max points buffered per node (Poisson(64): P(>256) ~ 0)

// Scratch (no allocations allowed): per-node counters + unordered index buckets.
__device__ int g_cnt[N_NODES];
__device__ int g_bucket[N_NODES * CAP];

// ---------------------------------------------------------------------------
// Kernel 0: reset per-node counters (graph replays reuse device globals).
// ---------------------------------------------------------------------------
__global__ void zero_cnt_kernel() {
    int i = blockIdx.x * blockDim.x + threadIdx.x;
    if (i < N_NODES) g_cnt[i] = 0;
}

// ---------------------------------------------------------------------------
// Kernel 1: 1-NN assign. One thread per point; all 2048 nodes cached in smem
// as float4 {nx, ny, nz, nn} with nn = (nx*nx + ny*ny) + nz*nz rounded exactly
// like jnp.sum(n*n, -1). Distance replicates the reference expansion:
//   d2 = (pp - 2*dot) + nn,   dot = fma(z,nz, fma(y,ny, x*nx))
// Strict '<' ascending scan => first-index tie-break (matches jnp.argmin).
// Also scatters the point index into its node's bucket (unordered; sorted later).
// ---------------------------------------------------------------------------
__global__ void __launch_bounds__(256) knn_kernel(
    const float* __restrict__ pts,
    const float* __restrict__ nodes,
    float* __restrict__ out_d2,
    float* __restrict__ out_id)
{
    __shared__ float4 sn[N_NODES];   // 32 KB

    const int tid = threadIdx.x;
    for (int j = tid; j < N_NODES; j += blockDim.x) {
        float nx = nodes[3 * j + 0];
        float ny = nodes[3 * j + 1];
        float nz = nodes[3 * j + 2];
        float nn = __fadd_rn(__fadd_rn(__fmul_rn(nx, nx), __fmul_rn(ny, ny)),
                             __fmul_rn(nz, nz));
        sn[j] = make_float4(nx, ny, nz, nn);
    }
    __syncthreads();

    const int i = blockIdx.x * blockDim.x + tid;
    const float x = pts[3 * i + 0];
    const float y = pts[3 * i + 1];
    const float z = pts[3 * i + 2];
    const float pp = __fadd_rn(__fadd_rn(__fmul_rn(x, x), __fmul_rn(y, y)),
                               __fmul_rn(z, z));

    float best = __int_as_float(0x7f800000);  // +inf
    int   bidx = 0;

#pragma unroll 8
    for (int j = 0; j < N_NODES; j++) {
        float4 n = sn[j];
        float dot = __fmaf_rn(z, n.z, __fmaf_rn(y, n.y, __fmul_rn(x, n.x)));
        // (pp - 2*dot): 2*dot is exact, so fma(-2,dot,pp) == round(pp - 2*dot)
        float d2 = __fadd_rn(__fmaf_rn(-2.0f, dot, pp), n.w);
        if (d2 < best) { best = d2; bidx = j; }
    }

    out_d2[i] = best;
    out_id[i] = (float)bidx;

    int pos = atomicAdd(&g_cnt[bidx], 1);
    if (pos < CAP) g_bucket[bidx * CAP + pos] = i;
}

// ---------------------------------------------------------------------------
// Kernel 2: per-node selection. One 256-thread block per node: bitonic-sort
// the (<=256) bucketed point indices ascending (pad INT_MAX), emit the first
// 32 (rank order == ascending point index == stable-argsort rank), pad with 0
// (reference's maximum(patch, 0) on the -1 fill).
// ---------------------------------------------------------------------------
__global__ void __launch_bounds__(CAP) select_kernel(float* __restrict__ out_patch) {
    __shared__ int s[CAP];
    const int node = blockIdx.x;
    const int tid  = threadIdx.x;
    const int cnt  = g_cnt[node];

    s[tid] = (tid < cnt) ? g_bucket[node * CAP + tid] : 0x7FFFFFFF;
    __syncthreads();

    for (int k = 2; k <= CAP; k <<= 1) {
        for (int j = k >> 1; j > 0; j >>= 1) {
            int ixj = tid ^ j;
            if (ixj > tid) {
                int a = s[tid], b = s[ixj];
                bool up = ((tid & k) == 0);
                if ((a > b) == up) { s[tid] = b; s[ixj] = a; }
            }
            __syncthreads();
        }
    }

    if (tid < K_SEL) {
        int v = s[tid];
        out_patch[node * K_SEL + tid] = (tid < cnt) ? (float)v : 0.0f;
    }
}

// ---------------------------------------------------------------------------
// Launch: outputs concatenated as [min_d2 | pcd_id | patch], all float32.
// ---------------------------------------------------------------------------
extern "C" void kernel_launch(void* const* d_in, const int* in_sizes, int n_in,
                              void* d_out, int out_size)
{
    const float* pts   = (const float*)d_in[0];   // [131072, 3]
    const float* nodes = (const float*)d_in[1];   // [2048, 3]
    // d_in[2] (neighbor_sel) is a compile-time constant here (32).

    float* out       = (float*)d_out;
    float* out_d2    = out;                        // 131072
    float* out_id    = out + N_POINTS;             // 131072
    float* out_patch = out + 2 * N_POINTS;         // 2048*32

    zero_cnt_kernel<<<(N_NODES + 255) / 256, 256>>>();
    knn_kernel<<<N_POINTS / 256, 256>>>(pts, nodes, out_d2, out_id);
    select_kernel<<<N_NODES, CAP>>>(out_patch);
}

// round 3
// speedup vs baseline: 1.0187x; 1.0187x over previous
#include <cuda_runtime.h>
#include <cuda_bf16.h>
#include <cstdint>

#define N_POINTS 131072
#define N_PAIRS  (N_POINTS / 2)
#define N_NODES  2048
#define K_SEL    32
#define CAP      256          // max points buffered per node (validated: no overflow on this input)
#define KNN_BLOCKS  296       // 2 blocks per SM on 148 SMs, balanced ranges
#define KNN_THREADS 256

typedef unsigned long long u64;

// Scratch (no allocations allowed): per-node counters + unordered index buckets.
// Zero-initialized at module load; select_kernel re-zeros g_cnt for graph replays.
__device__ int g_cnt[N_NODES];
__device__ int g_bucket[N_NODES * CAP];

// ---- packed f32x2 helpers (SASS FFMA2/FMUL2/FADD2 — per-lane RN, bit-identical
//      to scalar __fmaf_rn/__fmul_rn/__fadd_rn) -------------------------------
__device__ __forceinline__ u64 pk2(float lo, float hi) {
    u64 r; asm("mov.b64 %0, {%1, %2};" : "=l"(r) : "f"(lo), "f"(hi)); return r;
}
__device__ __forceinline__ void upk2(float& lo, float& hi, u64 v) {
    asm("mov.b64 {%0, %1}, %2;" : "=f"(lo), "=f"(hi) : "l"(v));
}
__device__ __forceinline__ u64 mul2(u64 a, u64 b) {
    u64 d; asm("mul.rn.f32x2 %0, %1, %2;" : "=l"(d) : "l"(a), "l"(b)); return d;
}
__device__ __forceinline__ u64 fma2(u64 a, u64 b, u64 c) {
    u64 d; asm("fma.rn.f32x2 %0, %1, %2, %3;" : "=l"(d) : "l"(a), "l"(b), "l"(c)); return d;
}
__device__ __forceinline__ u64 add2(u64 a, u64 b) {
    u64 d; asm("add.rn.f32x2 %0, %1, %2;" : "=l"(d) : "l"(a), "l"(b)); return d;
}

// ---------------------------------------------------------------------------
// Kernel 1: 1-NN assign, 2 points per thread via packed f32x2.
// Exact rounding chain preserved per lane:
//   r1=RN(x*nx); r2=RN(y*ny+r1); r3=RN(z*nz+r2); r4=RN(-2*r3+pp); d2=RN(r4+nn)
// Strict '<' ascending scan => first-index tie-break (matches jnp.argmin).
// Nodes cached in smem duplicated: s[4j..] = {(nx,nx),(ny,ny),(nz,nz),(nn,nn)}.
// ---------------------------------------------------------------------------
extern __shared__ u64 s_nodes[];   // N_NODES * 4 u64 = 64 KB

__global__ void __launch_bounds__(KNN_THREADS) knn_kernel(
    const float* __restrict__ pts,
    const float* __restrict__ nodes,
    float* __restrict__ out_d2,
    float* __restrict__ out_id)
{
    const int tid = threadIdx.x;

    // Fill duplicated node cache (exact nn rounding as reference sum order).
    for (int j = tid; j < N_NODES; j += KNN_THREADS) {
        float nx = nodes[3 * j + 0];
        float ny = nodes[3 * j + 1];
        float nz = nodes[3 * j + 2];
        float nn = __fadd_rn(__fadd_rn(__fmul_rn(nx, nx), __fmul_rn(ny, ny)),
                             __fmul_rn(nz, nz));
        s_nodes[4 * j + 0] = pk2(nx, nx);
        s_nodes[4 * j + 1] = pk2(ny, ny);
        s_nodes[4 * j + 2] = pk2(nz, nz);
        s_nodes[4 * j + 3] = pk2(nn, nn);
    }
    __syncthreads();

    // Balanced pair ranges: ~221-222 pairs per block, one pair per thread.
    const int b     = blockIdx.x;
    const int start = (int)(((long long)b       * N_PAIRS) / KNN_BLOCKS);
    const int end   = (int)(((long long)(b + 1) * N_PAIRS) / KNN_BLOCKS);
    const int p     = start + tid;
    if (p >= end) return;

    // Load two consecutive points (coalesced float2 loads).
    const float2* pf = (const float2*)pts;
    float2 f0 = pf[3 * p + 0];   // x0 y0
    float2 f1 = pf[3 * p + 1];   // z0 x1
    float2 f2 = pf[3 * p + 2];   // y1 z1
    const float x0 = f0.x, y0 = f0.y, z0 = f1.x;
    const float x1 = f1.y, y1 = f2.x, z1 = f2.y;

    const float pp0 = __fadd_rn(__fadd_rn(__fmul_rn(x0, x0), __fmul_rn(y0, y0)),
                                __fmul_rn(z0, z0));
    const float pp1 = __fadd_rn(__fadd_rn(__fmul_rn(x1, x1), __fmul_rn(y1, y1)),
                                __fmul_rn(z1, z1));

    const u64 X  = pk2(x0, x1);
    const u64 Y  = pk2(y0, y1);
    const u64 Z  = pk2(z0, z1);
    const u64 PP = pk2(pp0, pp1);
    const u64 NEG2 = pk2(-2.0f, -2.0f);

    float best0 = __int_as_float(0x7f800000);
    float best1 = __int_as_float(0x7f800000);
    int   i0 = 0, i1 = 0;

    const ulonglong2* sv = (const ulonglong2*)s_nodes;   // 2 x 16B per node

#pragma unroll 8
    for (int j = 0; j < N_NODES; j++) {
        ulonglong2 nA = sv[2 * j + 0];   // (nx,nx) (ny,ny)
        ulonglong2 nB = sv[2 * j + 1];   // (nz,nz) (nn,nn)
        u64 r = mul2(X, nA.x);
        r = fma2(Y, nA.y, r);
        r = fma2(Z, nB.x, r);
        r = fma2(NEG2, r, PP);           // -2*dot is exact scaling -> RN(pp-2dot)
        r = add2(r, nB.y);
        float d0, d1; upk2(d0, d1, r);
        if (d0 < best0) { best0 = d0; i0 = j; }
        if (d1 < best1) { best1 = d1; i1 = j; }
    }

    const int pt0 = 2 * p, pt1 = 2 * p + 1;
    out_d2[pt0] = best0;
    out_d2[pt1] = best1;
    out_id[pt0] = (float)i0;
    out_id[pt1] = (float)i1;

    int pos0 = atomicAdd(&g_cnt[i0], 1);
    if (pos0 < CAP) g_bucket[i0 * CAP + pos0] = pt0;
    int pos1 = atomicAdd(&g_cnt[i1], 1);
    if (pos1 < CAP) g_bucket[i1 * CAP + pos1] = pt1;
}

// ---------------------------------------------------------------------------
// Kernel 2: per-node selection. One 256-thread block per node: bitonic-sort
// the (<=256) bucketed point indices ascending (pad INT_MAX), emit the first
// 32 (ascending point index == stable-argsort rank), pad with 0.
// Also resets g_cnt for the next graph replay.
// ---------------------------------------------------------------------------
__global__ void __launch_bounds__(CAP) select_kernel(float* __restrict__ out_patch) {
    __shared__ int s[CAP];
    const int node = blockIdx.x;
    const int tid  = threadIdx.x;
    const int cnt  = g_cnt[node];

    s[tid] = (tid < cnt) ? g_bucket[node * CAP + tid] : 0x7FFFFFFF;
    __syncthreads();

    if (tid == 0) g_cnt[node] = 0;   // reset for next replay (after all threads read cnt)

    for (int k = 2; k <= CAP; k <<= 1) {
        for (int j = k >> 1; j > 0; j >>= 1) {
            int ixj = tid ^ j;
            if (ixj > tid) {
                int a = s[tid], bv = s[ixj];
                bool up = ((tid & k) == 0);
                if ((a > bv) == up) { s[tid] = bv; s[ixj] = a; }
            }
            __syncthreads();
        }
    }

    if (tid < K_SEL) {
        int v = s[tid];
        out_patch[node * K_SEL + tid] = (tid < cnt) ? (float)v : 0.0f;
    }
}

// ---------------------------------------------------------------------------
// Launch: outputs concatenated as [min_d2 | pcd_id | patch], all float32.
// ---------------------------------------------------------------------------
extern "C" void kernel_launch(void* const* d_in, const int* in_sizes, int n_in,
                              void* d_out, int out_size)
{
    const float* pts   = (const float*)d_in[0];   // [131072, 3]
    const float* nodes = (const float*)d_in[1];   // [2048, 3]

    float* out       = (float*)d_out;
    float* out_d2    = out;                        // 131072
    float* out_id    = out + N_POINTS;             // 131072
    float* out_patch = out + 2 * N_POINTS;         // 2048*32

    const size_t smem_bytes = (size_t)N_NODES * 4 * sizeof(u64);  // 64 KB
    (void)cudaFuncSetAttribute(knn_kernel,
                               cudaFuncAttributeMaxDynamicSharedMemorySize,
                               (int)smem_bytes);

    knn_kernel<<<KNN_BLOCKS, KNN_THREADS, smem_bytes>>>(pts, nodes, out_d2, out_id);
    select_kernel<<<N_NODES, CAP>>>(out_patch);
}

// round 5
// speedup vs baseline: 1.2096x; 1.1874x over previous
#include <cuda_runtime.h>
#include <cuda_bf16.h>
#include <cstdint>

#define N_POINTS 131072
#define N_PAIRS  (N_POINTS / 2)
#define N_NODES  2048
#define N_NPAIR  (N_NODES / 2)
#define K_SEL    32
#define CAP      256          // max points buffered per node (Poisson(64); overflow prob ~0)
#define KNN_BLOCKS  296       // 2 blocks/SM on 148 SMs, balanced ranges
#define KNN_THREADS 256

typedef unsigned long long u64;

// Scratch (no allocations allowed). Zero-initialized at load; select resets g_cnt.
__device__ int g_cnt[N_NODES];
__device__ int g_bucket[N_NODES * CAP];

// ---- packed f32x2 helpers (per-lane RN, bit-identical to scalar __f*_rn) ----
__device__ __forceinline__ u64 pk2(float lo, float hi) {
    u64 r; asm("mov.b64 %0, {%1, %2};" : "=l"(r) : "f"(lo), "f"(hi)); return r;
}
__device__ __forceinline__ void upk2(float& lo, float& hi, u64 v) {
    asm("mov.b64 {%0, %1}, %2;" : "=f"(lo), "=f"(hi) : "l"(v));
}
__device__ __forceinline__ u64 mul2(u64 a, u64 b) {
    u64 d; asm("mul.rn.f32x2 %0, %1, %2;" : "=l"(d) : "l"(a), "l"(b)); return d;
}
__device__ __forceinline__ u64 fma2(u64 a, u64 b, u64 c) {
    u64 d; asm("fma.rn.f32x2 %0, %1, %2, %3;" : "=l"(d) : "l"(a), "l"(b), "l"(c)); return d;
}
__device__ __forceinline__ u64 add2(u64 a, u64 b) {
    u64 d; asm("add.rn.f32x2 %0, %1, %2;" : "=l"(d) : "l"(a), "l"(b)); return d;
}

// ---------------------------------------------------------------------------
// Kernel 1: 1-NN assign. 2 points per thread, 2 NODES per packed f32x2 lane.
// Exact reference rounding chain per (point, node):
//   r1=RN(x*nx); r2=RN(y*ny+r1); r3=RN(z*nz+r2); r4=RN(-2*r3+pp); d2=RN(r4+nn)
// Node 2m is compared before node 2m+1 with strict '<' -> first-index tie-break
// identical to jnp.argmin's ascending scan.
// smem: per node-pair m: {(nx2m,nx2m+1),(ny..),(nz..),(nn..)} = 32B -> 32 KB.
// ---------------------------------------------------------------------------
extern __shared__ u64 s_nodes[];   // N_NPAIR * 4 u64 = 32 KB

__global__ void __launch_bounds__(KNN_THREADS) knn_kernel(
    const float* __restrict__ pts,
    const float* __restrict__ nodes,
    float* __restrict__ out_d2,
    float* __restrict__ out_id)
{
    const int tid = threadIdx.x;

    // Fill node-pair cache (exact nn rounding as reference sum order).
    for (int m = tid; m < N_NPAIR; m += KNN_THREADS) {
        const float2* nf = (const float2*)nodes;
        float2 f0 = nf[3 * m + 0];   // nxA nyA
        float2 f1 = nf[3 * m + 1];   // nzA nxB
        float2 f2 = nf[3 * m + 2];   // nyB nzB
        float nxA = f0.x, nyA = f0.y, nzA = f1.x;
        float nxB = f1.y, nyB = f2.x, nzB = f2.y;
        float nnA = __fadd_rn(__fadd_rn(__fmul_rn(nxA, nxA), __fmul_rn(nyA, nyA)),
                              __fmul_rn(nzA, nzA));
        float nnB = __fadd_rn(__fadd_rn(__fmul_rn(nxB, nxB), __fmul_rn(nyB, nyB)),
                              __fmul_rn(nzB, nzB));
        s_nodes[4 * m + 0] = pk2(nxA, nxB);
        s_nodes[4 * m + 1] = pk2(nyA, nyB);
        s_nodes[4 * m + 2] = pk2(nzA, nzB);
        s_nodes[4 * m + 3] = pk2(nnA, nnB);
    }
    __syncthreads();

    // Balanced pair ranges: ~221-222 point-pairs per block, one pair per thread.
    const int b     = blockIdx.x;
    const int start = (int)(((long long)b       * N_PAIRS) / KNN_BLOCKS);
    const int end   = (int)(((long long)(b + 1) * N_PAIRS) / KNN_BLOCKS);
    const int p     = start + tid;
    if (p >= end) return;

    // Two consecutive points (coalesced float2 loads).
    const float2* pf = (const float2*)pts;
    float2 f0 = pf[3 * p + 0];   // x0 y0
    float2 f1 = pf[3 * p + 1];   // z0 x1
    float2 f2 = pf[3 * p + 2];   // y1 z1
    const float x0 = f0.x, y0 = f0.y, z0 = f1.x;
    const float x1 = f1.y, y1 = f2.x, z1 = f2.y;

    const float pp0 = __fadd_rn(__fadd_rn(__fmul_rn(x0, x0), __fmul_rn(y0, y0)),
                                __fmul_rn(z0, z0));
    const float pp1 = __fadd_rn(__fadd_rn(__fmul_rn(x1, x1), __fmul_rn(y1, y1)),
                                __fmul_rn(z1, z1));

    // Per-point broadcast packs: both lanes = same point, lanes index node pair.
    const u64 X0 = pk2(x0, x0), Y0 = pk2(y0, y0), Z0 = pk2(z0, z0), PP0 = pk2(pp0, pp0);
    const u64 X1 = pk2(x1, x1), Y1 = pk2(y1, y1), Z1 = pk2(z1, z1), PP1 = pk2(pp1, pp1);
    const u64 NEG2 = pk2(-2.0f, -2.0f);

    float best0 = __int_as_float(0x7f800000);
    float best1 = __int_as_float(0x7f800000);
    int   i0 = 0, i1 = 0;

    const ulonglong2* sv = (const ulonglong2*)s_nodes;   // 2 x 16B per node-pair

#pragma unroll 8
    for (int m = 0; m < N_NPAIR; m++) {
        ulonglong2 a = sv[2 * m + 0];   // (nxA,nxB) (nyA,nyB)
        ulonglong2 c = sv[2 * m + 1];   // (nzA,nzB) (nnA,nnB)

        u64 r0 = mul2(X0, a.x);
        u64 r1 = mul2(X1, a.x);
        r0 = fma2(Y0, a.y, r0);
        r1 = fma2(Y1, a.y, r1);
        r0 = fma2(Z0, c.x, r0);
        r1 = fma2(Z1, c.x, r1);
        r0 = fma2(NEG2, r0, PP0);        // RN(pp - 2*dot): -2*dot exact scaling
        r1 = fma2(NEG2, r1, PP1);
        r0 = add2(r0, c.y);
        r1 = add2(r1, c.y);

        float dA0, dB0, dA1, dB1;
        upk2(dA0, dB0, r0);              // point0 vs nodes 2m, 2m+1
        upk2(dA1, dB1, r1);              // point1 vs nodes 2m, 2m+1

        const int j0 = 2 * m, j1 = 2 * m + 1;
        if (dA0 < best0) { best0 = dA0; i0 = j0; }
        if (dB0 < best0) { best0 = dB0; i0 = j1; }
        if (dA1 < best1) { best1 = dA1; i1 = j0; }
        if (dB1 < best1) { best1 = dB1; i1 = j1; }
    }

    const int pt0 = 2 * p, pt1 = 2 * p + 1;
    out_d2[pt0] = best0;
    out_d2[pt1] = best1;
    out_id[pt0] = (float)i0;
    out_id[pt1] = (float)i1;

    int pos0 = atomicAdd(&g_cnt[i0], 1);
    if (pos0 < CAP) g_bucket[i0 * CAP + pos0] = pt0;
    int pos1 = atomicAdd(&g_cnt[i1], 1);
    if (pos1 < CAP) g_bucket[i1 * CAP + pos1] = pt1;
}

// ---------------------------------------------------------------------------
// Kernel 2: per-node selection, ONE WARP per node, no __syncthreads.
// Lane holds 8 bucket slots -> in-register ascending sort (Batcher-8) ->
// 32 x { warp redux-min, record, shift matching lane's head } emits the 32
// smallest point indices in ascending order. Pad 0 beyond cnt.
// Also resets g_cnt for the next graph replay.
// ---------------------------------------------------------------------------
#define CE(a, b) { unsigned lo = min(a, b), hi = max(a, b); a = lo; b = hi; }

__global__ void __launch_bounds__(256) select_kernel(float* __restrict__ out_patch) {
    const int lane = threadIdx.x & 31;
    const int node = blockIdx.x * 8 + (threadIdx.x >> 5);
    const unsigned INF = 0x7FFFFFFFu;

    const int cnt = g_cnt[node];
    const int cl  = cnt < CAP ? cnt : CAP;
    if (lane == 0) g_cnt[node] = 0;      // reset for next replay (read precedes write in warp)

    const int base = node * CAP;
    unsigned e0 = (lane          < cl) ? (unsigned)g_bucket[base + lane          ] : INF;
    unsigned e1 = (lane + 32     < cl) ? (unsigned)g_bucket[base + lane + 32     ] : INF;
    unsigned e2 = (lane + 64     < cl) ? (unsigned)g_bucket[base + lane + 64     ] : INF;
    unsigned e3 = (lane + 96     < cl) ? (unsigned)g_bucket[base + lane + 96     ] : INF;
    unsigned e4 = (lane + 128    < cl) ? (unsigned)g_bucket[base + lane + 128    ] : INF;
    unsigned e5 = (lane + 160    < cl) ? (unsigned)g_bucket[base + lane + 160    ] : INF;
    unsigned e6 = (lane + 192    < cl) ? (unsigned)g_bucket[base + lane + 192    ] : INF;
    unsigned e7 = (lane + 224    < cl) ? (unsigned)g_bucket[base + lane + 224    ] : INF;

    // Batcher odd-even merge sort network for 8 (19 compare-exchanges).
    CE(e0, e1) CE(e2, e3) CE(e4, e5) CE(e6, e7)
    CE(e0, e2) CE(e1, e3) CE(e4, e6) CE(e5, e7)
    CE(e1, e2) CE(e5, e6)
    CE(e0, e4) CE(e1, e5) CE(e2, e6) CE(e3, e7)
    CE(e2, e4) CE(e3, e5)
    CE(e1, e2) CE(e3, e4) CE(e5, e6)

    unsigned keep = INF;
#pragma unroll
    for (int t = 0; t < K_SEL; t++) {
        unsigned m = __reduce_min_sync(0xFFFFFFFFu, e0);
        if (lane == t) keep = m;
        bool hit = (e0 == m);            // unique indices: at most one real hit
        e0 = hit ? e1 : e0;
        e1 = hit ? e2 : e1;
        e2 = hit ? e3 : e2;
        e3 = hit ? e4 : e3;
        e4 = hit ? e5 : e4;
        e5 = hit ? e6 : e5;
        e6 = hit ? e7 : e6;
        e7 = hit ? INF : e7;
    }

    out_patch[node * K_SEL + lane] = (lane < cl) ? (float)keep : 0.0f;
}

// ---------------------------------------------------------------------------
// Launch: outputs concatenated as [min_d2 | pcd_id | patch], all float32.
// ---------------------------------------------------------------------------
extern "C" void kernel_launch(void* const* d_in, const int* in_sizes, int n_in,
                              void* d_out, int out_size)
{
    const float* pts   = (const float*)d_in[0];   // [131072, 3]
    const float* nodes = (const float*)d_in[1];   // [2048, 3]

    float* out       = (float*)d_out;
    float* out_d2    = out;                        // 131072
    float* out_id    = out + N_POINTS;             // 131072
    float* out_patch = out + 2 * N_POINTS;         // 2048*32

    const size_t smem_bytes = (size_t)N_NPAIR * 4 * sizeof(u64);  // 32 KB
    (void)cudaFuncSetAttribute(knn_kernel,
                               cudaFuncAttributeMaxDynamicSharedMemorySize,
                               (int)smem_bytes);

    knn_kernel<<<KNN_BLOCKS, KNN_THREADS, smem_bytes>>>(pts, nodes, out_d2, out_id);
    select_kernel<<<N_NODES / 8, 256>>>(out_patch);
}

// round 6
// speedup vs baseline: 1.5807x; 1.3069x over previous
#include <cuda_runtime.h>
#include <cuda_bf16.h>
#include <cstdint>

#define N_POINTS 131072
#define N_PAIRS  (N_POINTS / 2)
#define N_NODES  2048
#define N_NPAIR  (N_NODES / 2)
#define N_GROUPS (N_NPAIR / 4)     // 256 groups of 4 node-pairs (8 nodes)
#define K_SEL    32
#define CAP      256               // max points buffered per node
#define KNN_BLOCKS  296            // 2 blocks/SM on 148 SMs, balanced ranges
#define KNN_THREADS 256

typedef unsigned long long u64;

// Scratch (no allocations allowed). Zero-initialized at load; select resets g_cnt.
__device__ int g_cnt[N_NODES];
__device__ int g_bucket[N_NODES * CAP];

// ---- packed f32x2 helpers (per-lane RN, bit-identical to scalar __f*_rn) ----
__device__ __forceinline__ u64 pk2(float lo, float hi) {
    u64 r; asm("mov.b64 %0, {%1, %2};" : "=l"(r) : "f"(lo), "f"(hi)); return r;
}
__device__ __forceinline__ void upk2(float& lo, float& hi, u64 v) {
    asm("mov.b64 {%0, %1}, %2;" : "=f"(lo), "=f"(hi) : "l"(v));
}
__device__ __forceinline__ u64 mul2(u64 a, u64 b) {
    u64 d; asm("mul.rn.f32x2 %0, %1, %2;" : "=l"(d) : "l"(a), "l"(b)); return d;
}
__device__ __forceinline__ u64 fma2(u64 a, u64 b, u64 c) {
    u64 d; asm("fma.rn.f32x2 %0, %1, %2, %3;" : "=l"(d) : "l"(a), "l"(b), "l"(c)); return d;
}
__device__ __forceinline__ u64 add2(u64 a, u64 b) {
    u64 d; asm("add.rn.f32x2 %0, %1, %2;" : "=l"(d) : "l"(a), "l"(b)); return d;
}

// Exact reference rounding chain (scalar), used for the recompute pass:
//   r1=RN(x*nx); r2=RN(y*ny+r1); r3=RN(z*nz+r2); r4=RN(-2*r3+pp); d2=RN(r4+nn)
__device__ __forceinline__ float d2_scalar(float x, float y, float z, float pp,
                                           float nx, float ny, float nz, float nn) {
    float r = __fmul_rn(x, nx);
    r = __fmaf_rn(y, ny, r);
    r = __fmaf_rn(z, nz, r);
    r = __fmaf_rn(-2.0f, r, pp);
    return __fadd_rn(r, nn);
}

// ---------------------------------------------------------------------------
// Kernel 1: 1-NN assign. 2 points/thread, 2 nodes per packed f32x2 lane,
// tournament argmin over groups of 4 node-pairs (8 nodes):
//   - fmin tree (FMNMX, alu pipe) gives the group min value
//   - strict '<' vs running best records the FIRST group containing the min
//   - post-loop: recompute the winning group's 8 d2 bit-exactly, first index
//     among equal hits == jnp.argmin's ascending first-index tie-break.
// ---------------------------------------------------------------------------
extern __shared__ u64 s_nodes[];   // N_NPAIR * 4 u64 = 32 KB

__global__ void __launch_bounds__(KNN_THREADS) knn_kernel(
    const float* __restrict__ pts,
    const float* __restrict__ nodes,
    float* __restrict__ out_d2,
    float* __restrict__ out_id)
{
    const int tid = threadIdx.x;

    // Fill node-pair cache (exact nn rounding as reference sum order).
    for (int m = tid; m < N_NPAIR; m += KNN_THREADS) {
        const float2* nf = (const float2*)nodes;
        float2 f0 = nf[3 * m + 0];   // nxA nyA
        float2 f1 = nf[3 * m + 1];   // nzA nxB
        float2 f2 = nf[3 * m + 2];   // nyB nzB
        float nxA = f0.x, nyA = f0.y, nzA = f1.x;
        float nxB = f1.y, nyB = f2.x, nzB = f2.y;
        float nnA = __fadd_rn(__fadd_rn(__fmul_rn(nxA, nxA), __fmul_rn(nyA, nyA)),
                              __fmul_rn(nzA, nzA));
        float nnB = __fadd_rn(__fadd_rn(__fmul_rn(nxB, nxB), __fmul_rn(nyB, nyB)),
                              __fmul_rn(nzB, nzB));
        s_nodes[4 * m + 0] = pk2(nxA, nxB);
        s_nodes[4 * m + 1] = pk2(nyA, nyB);
        s_nodes[4 * m + 2] = pk2(nzA, nzB);
        s_nodes[4 * m + 3] = pk2(nnA, nnB);
    }
    __syncthreads();

    // Balanced point-pair ranges: ~221-222 pairs per block, one per thread.
    const int b     = blockIdx.x;
    const int start = (int)(((long long)b       * N_PAIRS) / KNN_BLOCKS);
    const int end   = (int)(((long long)(b + 1) * N_PAIRS) / KNN_BLOCKS);
    const int p     = start + tid;
    if (p >= end) return;

    // Two consecutive points (coalesced float2 loads).
    const float2* pf = (const float2*)pts;
    float2 f0 = pf[3 * p + 0];
    float2 f1 = pf[3 * p + 1];
    float2 f2 = pf[3 * p + 2];
    const float x0 = f0.x, y0 = f0.y, z0 = f1.x;
    const float x1 = f1.y, y1 = f2.x, z1 = f2.y;

    const float pp0 = __fadd_rn(__fadd_rn(__fmul_rn(x0, x0), __fmul_rn(y0, y0)),
                                __fmul_rn(z0, z0));
    const float pp1 = __fadd_rn(__fadd_rn(__fmul_rn(x1, x1), __fmul_rn(y1, y1)),
                                __fmul_rn(z1, z1));

    const u64 X0 = pk2(x0, x0), Y0 = pk2(y0, y0), Z0 = pk2(z0, z0), PP0 = pk2(pp0, pp0);
    const u64 X1 = pk2(x1, x1), Y1 = pk2(y1, y1), Z1 = pk2(z1, z1), PP1 = pk2(pp1, pp1);
    const u64 NEG2 = pk2(-2.0f, -2.0f);

    float best0 = __int_as_float(0x7f800000);
    float best1 = __int_as_float(0x7f800000);
    int   grp0 = 0, grp1 = 0;

    const ulonglong2* sv = (const ulonglong2*)s_nodes;   // 2 x 16B per node-pair

#pragma unroll 2
    for (int g = 0; g < N_GROUPS; g++) {
        // Load 4 node-pairs (8 nodes) for this group.
        ulonglong2 a0 = sv[8 * g + 0], c0 = sv[8 * g + 1];
        ulonglong2 a1 = sv[8 * g + 2], c1 = sv[8 * g + 3];
        ulonglong2 a2 = sv[8 * g + 4], c2 = sv[8 * g + 5];
        ulonglong2 a3 = sv[8 * g + 6], c3 = sv[8 * g + 7];

        // Point 0 vs 8 nodes (4 packed chains).
        u64 q0 = add2(fma2(NEG2, fma2(Z0, c0.x, fma2(Y0, a0.y, mul2(X0, a0.x))), PP0), c0.y);
        u64 q1 = add2(fma2(NEG2, fma2(Z0, c1.x, fma2(Y0, a1.y, mul2(X0, a1.x))), PP0), c1.y);
        u64 q2 = add2(fma2(NEG2, fma2(Z0, c2.x, fma2(Y0, a2.y, mul2(X0, a2.x))), PP0), c2.y);
        u64 q3 = add2(fma2(NEG2, fma2(Z0, c3.x, fma2(Y0, a3.y, mul2(X0, a3.x))), PP0), c3.y);
        // Point 1 vs same 8 nodes.
        u64 s0 = add2(fma2(NEG2, fma2(Z1, c0.x, fma2(Y1, a0.y, mul2(X1, a0.x))), PP1), c0.y);
        u64 s1 = add2(fma2(NEG2, fma2(Z1, c1.x, fma2(Y1, a1.y, mul2(X1, a1.x))), PP1), c1.y);
        u64 s2 = add2(fma2(NEG2, fma2(Z1, c2.x, fma2(Y1, a2.y, mul2(X1, a2.x))), PP1), c2.y);
        u64 s3 = add2(fma2(NEG2, fma2(Z1, c3.x, fma2(Y1, a3.y, mul2(X1, a3.x))), PP1), c3.y);

        float qa0, qb0, qa1, qb1, qa2, qb2, qa3, qb3;
        upk2(qa0, qb0, q0); upk2(qa1, qb1, q1);
        upk2(qa2, qb2, q2); upk2(qa3, qb3, q3);
        float t0 = fminf(fminf(fminf(qa0, qb0), fminf(qa1, qb1)),
                         fminf(fminf(qa2, qb2), fminf(qa3, qb3)));

        float sa0, sb0, sa1, sb1, sa2, sb2, sa3, sb3;
        upk2(sa0, sb0, s0); upk2(sa1, sb1, s1);
        upk2(sa2, sb2, s2); upk2(sa3, sb3, s3);
        float t1 = fminf(fminf(fminf(sa0, sb0), fminf(sa1, sb1)),
                         fminf(fminf(sa2, sb2), fminf(sa3, sb3)));

        if (t0 < best0) { best0 = t0; grp0 = g; }   // strict '<': first group w/ min
        if (t1 < best1) { best1 = t1; grp1 = g; }
    }

    // Recompute the winning group's 8 d2 bit-exactly; first index among equal
    // hits (ascending j) == reference argmin tie-break.
    int i0 = 0x7FFFFFFF, i1 = 0x7FFFFFFF;
#pragma unroll
    for (int t = 0; t < 4; t++) {
        {
            int m = 4 * grp0 + t;
            ulonglong2 a = sv[2 * m + 0], c = sv[2 * m + 1];
            float nxA, nxB, nyA, nyB, nzA, nzB, nnA, nnB;
            upk2(nxA, nxB, a.x); upk2(nyA, nyB, a.y);
            upk2(nzA, nzB, c.x); upk2(nnA, nnB, c.y);
            float dA = d2_scalar(x0, y0, z0, pp0, nxA, nyA, nzA, nnA);
            float dB = d2_scalar(x0, y0, z0, pp0, nxB, nyB, nzB, nnB);
            if (dA == best0) i0 = min(i0, 2 * m);
            if (dB == best0) i0 = min(i0, 2 * m + 1);
        }
        {
            int m = 4 * grp1 + t;
            ulonglong2 a = sv[2 * m + 0], c = sv[2 * m + 1];
            float nxA, nxB, nyA, nyB, nzA, nzB, nnA, nnB;
            upk2(nxA, nxB, a.x); upk2(nyA, nyB, a.y);
            upk2(nzA, nzB, c.x); upk2(nnA, nnB, c.y);
            float dA = d2_scalar(x1, y1, z1, pp1, nxA, nyA, nzA, nnA);
            float dB = d2_scalar(x1, y1, z1, pp1, nxB, nyB, nzB, nnB);
            if (dA == best1) i1 = min(i1, 2 * m);
            if (dB == best1) i1 = min(i1, 2 * m + 1);
        }
    }

    const int pt0 = 2 * p, pt1 = 2 * p + 1;
    out_d2[pt0] = best0;
    out_d2[pt1] = best1;
    out_id[pt0] = (float)i0;
    out_id[pt1] = (float)i1;

    int pos0 = atomicAdd(&g_cnt[i0], 1);
    if (pos0 < CAP) g_bucket[i0 * CAP + pos0] = pt0;
    int pos1 = atomicAdd(&g_cnt[i1], 1);
    if (pos1 < CAP) g_bucket[i1 * CAP + pos1] = pt1;
}

// ---------------------------------------------------------------------------
// Kernel 2: per-node selection, one warp per node (proven 6.5us at R5).
// ---------------------------------------------------------------------------
#define CE(a, b) { unsigned lo = min(a, b), hi = max(a, b); a = lo; b = hi; }

__global__ void __launch_bounds__(256) select_kernel(float* __restrict__ out_patch) {
    const int lane = threadIdx.x & 31;
    const int node = blockIdx.x * 8 + (threadIdx.x >> 5);
    const unsigned INF = 0x7FFFFFFFu;

    const int cnt = g_cnt[node];
    const int cl  = cnt < CAP ? cnt : CAP;
    if (lane == 0) g_cnt[node] = 0;      // reset for next graph replay

    const int base = node * CAP;
    unsigned e0 = (lane       < cl) ? (unsigned)g_bucket[base + lane      ] : INF;
    unsigned e1 = (lane + 32  < cl) ? (unsigned)g_bucket[base + lane + 32 ] : INF;
    unsigned e2 = (lane + 64  < cl) ? (unsigned)g_bucket[base + lane + 64 ] : INF;
    unsigned e3 = (lane + 96  < cl) ? (unsigned)g_bucket[base + lane + 96 ] : INF;
    unsigned e4 = (lane + 128 < cl) ? (unsigned)g_bucket[base + lane + 128] : INF;
    unsigned e5 = (lane + 160 < cl) ? (unsigned)g_bucket[base + lane + 160] : INF;
    unsigned e6 = (lane + 192 < cl) ? (unsigned)g_bucket[base + lane + 192] : INF;
    unsigned e7 = (lane + 224 < cl) ? (unsigned)g_bucket[base + lane + 224] : INF;

    // Batcher odd-even merge sort network for 8 (19 compare-exchanges).
    CE(e0, e1) CE(e2, e3) CE(e4, e5) CE(e6, e7)
    CE(e0, e2) CE(e1, e3) CE(e4, e6) CE(e5, e7)
    CE(e1, e2) CE(e5, e6)
    CE(e0, e4) CE(e1, e5) CE(e2, e6) CE(e3, e7)
    CE(e2, e4) CE(e3, e5)
    CE(e1, e2) CE(e3, e4) CE(e5, e6)

    unsigned keep = INF;
#pragma unroll
    for (int t = 0; t < K_SEL; t++) {
        unsigned m = __reduce_min_sync(0xFFFFFFFFu, e0);
        if (lane == t) keep = m;
        bool hit = (e0 == m);            // unique indices: at most one real hit
        e0 = hit ? e1 : e0;
        e1 = hit ? e2 : e1;
        e2 = hit ? e3 : e2;
        e3 = hit ? e4 : e3;
        e4 = hit ? e5 : e4;
        e5 = hit ? e6 : e5;
        e6 = hit ? e7 : e6;
        e7 = hit ? INF : e7;
    }

    out_patch[node * K_SEL + lane] = (lane < cl) ? (float)keep : 0.0f;
}

// ---------------------------------------------------------------------------
// Launch: outputs concatenated as [min_d2 | pcd_id | patch], all float32.
// ---------------------------------------------------------------------------
extern "C" void kernel_launch(void* const* d_in, const int* in_sizes, int n_in,
                              void* d_out, int out_size)
{
    const float* pts   = (const float*)d_in[0];   // [131072, 3]
    const float* nodes = (const float*)d_in[1];   // [2048, 3]

    float* out       = (float*)d_out;
    float* out_d2    = out;                        // 131072
    float* out_id    = out + N_POINTS;             // 131072
    float* out_patch = out + 2 * N_POINTS;         // 2048*32

    const size_t smem_bytes = (size_t)N_NPAIR * 4 * sizeof(u64);  // 32 KB
    (void)cudaFuncSetAttribute(knn_kernel,
                               cudaFuncAttributeMaxDynamicSharedMemorySize,
                               (int)smem_bytes);

    knn_kernel<<<KNN_BLOCKS, KNN_THREADS, smem_bytes>>>(pts, nodes, out_d2, out_id);
    select_kernel<<<N_NODES / 8, 256>>>(out_patch);
}

// round 7
// speedup vs baseline: 1.6324x; 1.0327x over previous
#include <cuda_runtime.h>
#include <cuda_bf16.h>
#include <cstdint>

#define N_POINTS 131072
#define N_PAIRS  (N_POINTS / 2)
#define N_NODES  2048
#define N_NPAIR  (N_NODES / 2)
#define N_GROUPS (N_NPAIR / 4)     // 256 groups of 4 node-pairs (8 nodes)
#define K_SEL    32
#define CAP      256               // max points buffered per node
#define KNN_BLOCKS  296            // 2 blocks/SM on 148 SMs, balanced ranges
#define KNN_THREADS 256

typedef unsigned long long u64;

// Scratch (no allocations allowed). Zero-initialized at load; select resets g_cnt.
__device__ int g_cnt[N_NODES];
__device__ int g_bucket[N_NODES * CAP];

// ---- packed f32x2 helpers (per-lane RN, bit-identical to scalar __f*_rn) ----
__device__ __forceinline__ u64 pk2(float lo, float hi) {
    u64 r; asm("mov.b64 %0, {%1, %2};" : "=l"(r) : "f"(lo), "f"(hi)); return r;
}
__device__ __forceinline__ void upk2(float& lo, float& hi, u64 v) {
    asm("mov.b64 {%0, %1}, %2;" : "=f"(lo), "=f"(hi) : "l"(v));
}
__device__ __forceinline__ u64 mul2(u64 a, u64 b) {
    u64 d; asm("mul.rn.f32x2 %0, %1, %2;" : "=l"(d) : "l"(a), "l"(b)); return d;
}
__device__ __forceinline__ u64 fma2(u64 a, u64 b, u64 c) {
    u64 d; asm("fma.rn.f32x2 %0, %1, %2, %3;" : "=l"(d) : "l"(a), "l"(b), "l"(c)); return d;
}
__device__ __forceinline__ u64 add2(u64 a, u64 b) {
    u64 d; asm("add.rn.f32x2 %0, %1, %2;" : "=l"(d) : "l"(a), "l"(b)); return d;
}

// Exact reference rounding chain (scalar), used for the recompute pass:
//   r1=RN(x*nx); r2=RN(y*ny+r1); r3=RN(z*nz+r2); r4=RN(-2*r3+pp); d2=RN(r4+nn)
__device__ __forceinline__ float d2_scalar(float x, float y, float z, float pp,
                                           float nx, float ny, float nz, float nn) {
    float r = __fmul_rn(x, nx);
    r = __fmaf_rn(y, ny, r);
    r = __fmaf_rn(z, nz, r);
    r = __fmaf_rn(-2.0f, r, pp);
    return __fadd_rn(r, nn);
}

// ---------------------------------------------------------------------------
// Kernel 1: 1-NN assign. 2 points/thread, 2 nodes per packed f32x2 lane,
// tournament argmin over groups of 4 node-pairs (8 nodes).
// Main-loop chain uses exact -2 pre-scaling of the point coordinates:
//   s1=RN((-2x)*nx) = -2*RN(x*nx)            (scaling by 2 is exact, RN-commutes)
//   s2=RN((-2y)*ny+s1) = -2*RN(y*ny+r1)
//   s3=RN((-2z)*nz+s2) = -2*r3
//   r4=RN(s3+pp) = RN(pp-2*r3)   [FADD2, rt=2, replaces rt=3 FFMA2]
//   d2=RN(r4+nn)
// => bit-identical to the reference chain, one fewer rt=3 op on the fma pipe.
// ---------------------------------------------------------------------------
extern __shared__ u64 s_nodes[];   // N_NPAIR * 4 u64 = 32 KB

__global__ void __launch_bounds__(KNN_THREADS, 2) knn_kernel(
    const float* __restrict__ pts,
    const float* __restrict__ nodes,
    float* __restrict__ out_d2,
    float* __restrict__ out_id)
{
    const int tid = threadIdx.x;

    // Fill node-pair cache (exact nn rounding as reference sum order).
    for (int m = tid; m < N_NPAIR; m += KNN_THREADS) {
        const float2* nf = (const float2*)nodes;
        float2 f0 = nf[3 * m + 0];   // nxA nyA
        float2 f1 = nf[3 * m + 1];   // nzA nxB
        float2 f2 = nf[3 * m + 2];   // nyB nzB
        float nxA = f0.x, nyA = f0.y, nzA = f1.x;
        float nxB = f1.y, nyB = f2.x, nzB = f2.y;
        float nnA = __fadd_rn(__fadd_rn(__fmul_rn(nxA, nxA), __fmul_rn(nyA, nyA)),
                              __fmul_rn(nzA, nzA));
        float nnB = __fadd_rn(__fadd_rn(__fmul_rn(nxB, nxB), __fmul_rn(nyB, nyB)),
                              __fmul_rn(nzB, nzB));
        s_nodes[4 * m + 0] = pk2(nxA, nxB);
        s_nodes[4 * m + 1] = pk2(nyA, nyB);
        s_nodes[4 * m + 2] = pk2(nzA, nzB);
        s_nodes[4 * m + 3] = pk2(nnA, nnB);
    }
    __syncthreads();

    // Balanced point-pair ranges: ~221-222 pairs per block, one per thread.
    const int b     = blockIdx.x;
    const int start = (int)(((long long)b       * N_PAIRS) / KNN_BLOCKS);
    const int end   = (int)(((long long)(b + 1) * N_PAIRS) / KNN_BLOCKS);
    const int p     = start + tid;
    if (p >= end) return;

    // Two consecutive points (coalesced float2 loads).
    const float2* pf = (const float2*)pts;
    float2 f0 = pf[3 * p + 0];
    float2 f1 = pf[3 * p + 1];
    float2 f2 = pf[3 * p + 2];
    const float x0 = f0.x, y0 = f0.y, z0 = f1.x;
    const float x1 = f1.y, y1 = f2.x, z1 = f2.y;

    const float pp0 = __fadd_rn(__fadd_rn(__fmul_rn(x0, x0), __fmul_rn(y0, y0)),
                                __fmul_rn(z0, z0));
    const float pp1 = __fadd_rn(__fadd_rn(__fmul_rn(x1, x1), __fmul_rn(y1, y1)),
                                __fmul_rn(z1, z1));

    // Exact -2 pre-scaled coordinates (exponent shift, no rounding).
    const float x0m = -2.0f * x0, y0m = -2.0f * y0, z0m = -2.0f * z0;
    const float x1m = -2.0f * x1, y1m = -2.0f * y1, z1m = -2.0f * z1;

    const u64 X0 = pk2(x0m, x0m), Y0 = pk2(y0m, y0m), Z0 = pk2(z0m, z0m), PP0 = pk2(pp0, pp0);
    const u64 X1 = pk2(x1m, x1m), Y1 = pk2(y1m, y1m), Z1 = pk2(z1m, z1m), PP1 = pk2(pp1, pp1);

    float best0 = __int_as_float(0x7f800000);
    float best1 = __int_as_float(0x7f800000);
    int   grp0 = 0, grp1 = 0;

    const ulonglong2* sv = (const ulonglong2*)s_nodes;   // 2 x 16B per node-pair

#pragma unroll 2
    for (int g = 0; g < N_GROUPS; g++) {
        // Load 4 node-pairs (8 nodes) for this group.
        ulonglong2 a0 = sv[8 * g + 0], c0 = sv[8 * g + 1];
        ulonglong2 a1 = sv[8 * g + 2], c1 = sv[8 * g + 3];
        ulonglong2 a2 = sv[8 * g + 4], c2 = sv[8 * g + 5];
        ulonglong2 a3 = sv[8 * g + 6], c3 = sv[8 * g + 7];

        // Point 0 vs 8 nodes (4 packed chains): mul2,fma2,fma2,add2,add2.
        u64 q0 = add2(add2(fma2(Z0, c0.x, fma2(Y0, a0.y, mul2(X0, a0.x))), PP0), c0.y);
        u64 q1 = add2(add2(fma2(Z0, c1.x, fma2(Y0, a1.y, mul2(X0, a1.x))), PP0), c1.y);
        u64 q2 = add2(add2(fma2(Z0, c2.x, fma2(Y0, a2.y, mul2(X0, a2.x))), PP0), c2.y);
        u64 q3 = add2(add2(fma2(Z0, c3.x, fma2(Y0, a3.y, mul2(X0, a3.x))), PP0), c3.y);
        // Point 1 vs same 8 nodes.
        u64 s0 = add2(add2(fma2(Z1, c0.x, fma2(Y1, a0.y, mul2(X1, a0.x))), PP1), c0.y);
        u64 s1 = add2(add2(fma2(Z1, c1.x, fma2(Y1, a1.y, mul2(X1, a1.x))), PP1), c1.y);
        u64 s2 = add2(add2(fma2(Z1, c2.x, fma2(Y1, a2.y, mul2(X1, a2.x))), PP1), c2.y);
        u64 s3 = add2(add2(fma2(Z1, c3.x, fma2(Y1, a3.y, mul2(X1, a3.x))), PP1), c3.y);

        float qa0, qb0, qa1, qb1, qa2, qb2, qa3, qb3;
        upk2(qa0, qb0, q0); upk2(qa1, qb1, q1);
        upk2(qa2, qb2, q2); upk2(qa3, qb3, q3);
        float t0 = fminf(fminf(fminf(qa0, qb0), fminf(qa1, qb1)),
                         fminf(fminf(qa2, qb2), fminf(qa3, qb3)));

        float sa0, sb0, sa1, sb1, sa2, sb2, sa3, sb3;
        upk2(sa0, sb0, s0); upk2(sa1, sb1, s1);
        upk2(sa2, sb2, s2); upk2(sa3, sb3, s3);
        float t1 = fminf(fminf(fminf(sa0, sb0), fminf(sa1, sb1)),
                         fminf(fminf(sa2, sb2), fminf(sa3, sb3)));

        if (t0 < best0) { best0 = t0; grp0 = g; }   // strict '<': first group w/ min
        if (t1 < best1) { best1 = t1; grp1 = g; }
    }

    // Recompute the winning group's 8 d2 bit-exactly (reference chain); first
    // index among equal hits (ascending j) == reference argmin tie-break.
    int i0 = 0x7FFFFFFF, i1 = 0x7FFFFFFF;
#pragma unroll
    for (int t = 0; t < 4; t++) {
        {
            int m = 4 * grp0 + t;
            ulonglong2 a = sv[2 * m + 0], c = sv[2 * m + 1];
            float nxA, nxB, nyA, nyB, nzA, nzB, nnA, nnB;
            upk2(nxA, nxB, a.x); upk2(nyA, nyB, a.y);
            upk2(nzA, nzB, c.x); upk2(nnA, nnB, c.y);
            float dA = d2_scalar(x0, y0, z0, pp0, nxA, nyA, nzA, nnA);
            float dB = d2_scalar(x0, y0, z0, pp0, nxB, nyB, nzB, nnB);
            if (dA == best0) i0 = min(i0, 2 * m);
            if (dB == best0) i0 = min(i0, 2 * m + 1);
        }
        {
            int m = 4 * grp1 + t;
            ulonglong2 a = sv[2 * m + 0], c = sv[2 * m + 1];
            float nxA, nxB, nyA, nyB, nzA, nzB, nnA, nnB;
            upk2(nxA, nxB, a.x); upk2(nyA, nyB, a.y);
            upk2(nzA, nzB, c.x); upk2(nnA, nnB, c.y);
            float dA = d2_scalar(x1, y1, z1, pp1, nxA, nyA, nzA, nnA);
            float dB = d2_scalar(x1, y1, z1, pp1, nxB, nyB, nzB, nnB);
            if (dA == best1) i1 = min(i1, 2 * m);
            if (dB == best1) i1 = min(i1, 2 * m + 1);
        }
    }

    const int pt0 = 2 * p, pt1 = 2 * p + 1;
    out_d2[pt0] = best0;
    out_d2[pt1] = best1;
    out_id[pt0] = (float)i0;
    out_id[pt1] = (float)i1;

    int pos0 = atomicAdd(&g_cnt[i0], 1);
    if (pos0 < CAP) g_bucket[i0 * CAP + pos0] = pt0;
    int pos1 = atomicAdd(&g_cnt[i1], 1);
    if (pos1 < CAP) g_bucket[i1 * CAP + pos1] = pt1;
}

// ---------------------------------------------------------------------------
// Kernel 2: per-node selection, one warp per node (proven 6.5-7.2us).
// ---------------------------------------------------------------------------
#define CE(a, b) { unsigned lo = min(a, b), hi = max(a, b); a = lo; b = hi; }

__global__ void __launch_bounds__(256) select_kernel(float* __restrict__ out_patch) {
    const int lane = threadIdx.x & 31;
    const int node = blockIdx.x * 8 + (threadIdx.x >> 5);
    const unsigned INF = 0x7FFFFFFFu;

    const int cnt = g_cnt[node];
    const int cl  = cnt < CAP ? cnt : CAP;
    if (lane == 0) g_cnt[node] = 0;      // reset for next graph replay

    const int base = node * CAP;
    unsigned e0 = (lane       < cl) ? (unsigned)g_bucket[base + lane      ] : INF;
    unsigned e1 = (lane + 32  < cl) ? (unsigned)g_bucket[base + lane + 32 ] : INF;
    unsigned e2 = (lane + 64  < cl) ? (unsigned)g_bucket[base + lane + 64 ] : INF;
    unsigned e3 = (lane + 96  < cl) ? (unsigned)g_bucket[base + lane + 96 ] : INF;
    unsigned e4 = (lane + 128 < cl) ? (unsigned)g_bucket[base + lane + 128] : INF;
    unsigned e5 = (lane + 160 < cl) ? (unsigned)g_bucket[base + lane + 160] : INF;
    unsigned e6 = (lane + 192 < cl) ? (unsigned)g_bucket[base + lane + 192] : INF;
    unsigned e7 = (lane + 224 < cl) ? (unsigned)g_bucket[base + lane + 224] : INF;

    // Batcher odd-even merge sort network for 8 (19 compare-exchanges).
    CE(e0, e1) CE(e2, e3) CE(e4, e5) CE(e6, e7)
    CE(e0, e2) CE(e1, e3) CE(e4, e6) CE(e5, e7)
    CE(e1, e2) CE(e5, e6)
    CE(e0, e4) CE(e1, e5) CE(e2, e6) CE(e3, e7)
    CE(e2, e4) CE(e3, e5)
    CE(e1, e2) CE(e3, e4) CE(e5, e6)

    unsigned keep = INF;
#pragma unroll
    for (int t = 0; t < K_SEL; t++) {
        unsigned m = __reduce_min_sync(0xFFFFFFFFu, e0);
        if (lane == t) keep = m;
        bool hit = (e0 == m);            // unique indices: at most one real hit
        e0 = hit ? e1 : e0;
        e1 = hit ? e2 : e1;
        e2 = hit ? e3 : e2;
        e3 = hit ? e4 : e3;
        e4 = hit ? e5 : e4;
        e5 = hit ? e6 : e5;
        e6 = hit ? e7 : e6;
        e7 = hit ? INF : e7;
    }

    out_patch[node * K_SEL + lane] = (lane < cl) ? (float)keep : 0.0f;
}

// ---------------------------------------------------------------------------
// Launch: outputs concatenated as [min_d2 | pcd_id | patch], all float32.
// ---------------------------------------------------------------------------
extern "C" void kernel_launch(void* const* d_in, const int* in_sizes, int n_in,
                              void* d_out, int out_size)
{
    const float* pts   = (const float*)d_in[0];   // [131072, 3]
    const float* nodes = (const float*)d_in[1];   // [2048, 3]

    float* out       = (float*)d_out;
    float* out_d2    = out;                        // 131072
    float* out_id    = out + N_POINTS;             // 131072
    float* out_patch = out + 2 * N_POINTS;         // 2048*32

    const size_t smem_bytes = (size_t)N_NPAIR * 4 * sizeof(u64);  // 32 KB
    (void)cudaFuncSetAttribute(knn_kernel,
                               cudaFuncAttributeMaxDynamicSharedMemorySize,
                               (int)smem_bytes);

    knn_kernel<<<KNN_BLOCKS, KNN_THREADS, smem_bytes>>>(pts, nodes, out_d2, out_id);
    select_kernel<<<N_NODES / 8, 256>>>(out_patch);
}